// round 7
// baseline (speedup 1.0000x reference)
#include <cuda_runtime.h>
#include <math.h>
#include <stdint.h>

#define FULL 0xffffffffu

// Problem constants
#define Bz 2
#define Sdim 2048
#define Edim 256
#define Hn 8
#define HD 32
#define WIN 129
#define OFF 64
#define MTOK (Bz*Sdim)          // 4096 token rows
#define WSZ (Edim*Edim)         // 65536

// Scratch (no cudaMalloc allowed)
__device__ float g_xh[MTOK*Edim];   // xpe hi (tf32-rounded)
__device__ float g_xl[MTOK*Edim];   // xpe lo
__device__ float g_q[MTOK*Edim];
__device__ float g_k[MTOK*Edim];
__device__ float g_v[MTOK*Edim];
__device__ float g_ch[MTOK*Edim];   // ctx hi
__device__ float g_cl[MTOK*Edim];   // ctx lo
__device__ float g_wh[4*WSZ];       // Wq,Wk,Wv,Wo hi
__device__ float g_wl[4*WSZ];       // lo

__device__ __forceinline__ void split_tf32(float x, uint32_t& hi, uint32_t& lo) {
    asm("cvt.rna.tf32.f32 %0, %1;" : "=r"(hi) : "f"(x));
    float l = x - __uint_as_float(hi);
    asm("cvt.rna.tf32.f32 %0, %1;" : "=r"(lo) : "f"(l));
}

// ---------------------------------------------------------------------------
// x + sinusoidal positional encoding -> pre-split hi/lo
// ---------------------------------------------------------------------------
__global__ void add_pe_kernel(const float* __restrict__ x,
                              float* __restrict__ yh, float* __restrict__ yl) {
    int i = blockIdx.x * 256 + threadIdx.x;
    int e = i & (Edim - 1);
    int s = (i >> 8) & (Sdim - 1);
    float dv = expf((float)(e >> 1) * (-2.0f * 9.210340371976184f / 256.0f));
    float ang = (float)s * dv;
    float pe = (e & 1) ? cosf(ang) : sinf(ang);
    float y = x[i] + pe;
    uint32_t hi, lo;
    split_tf32(y, hi, lo);
    yh[i] = __uint_as_float(hi);
    yl[i] = __uint_as_float(lo);
}

// ---------------------------------------------------------------------------
// Split the 4 weight matrices into tf32 hi/lo pairs (once per launch)
// ---------------------------------------------------------------------------
__global__ void split_w_kernel(const float* __restrict__ Wq, const float* __restrict__ Wk,
                               const float* __restrict__ Wv, const float* __restrict__ Wo,
                               float* __restrict__ wh, float* __restrict__ wl) {
    int i = blockIdx.x * 256 + threadIdx.x;      // 4*WSZ threads
    int wsel = i >> 16;
    int off  = i & (WSZ - 1);
    const float* W = (wsel == 0) ? Wq : ((wsel == 1) ? Wk : ((wsel == 2) ? Wv : Wo));
    uint32_t hi, lo;
    split_tf32(W[off], hi, lo);
    wh[i] = __uint_as_float(hi);
    wl[i] = __uint_as_float(lo);
}

// ---------------------------------------------------------------------------
// 3xTF32 tensor-core GEMM on PRE-SPLIT operands:
//   Y = Xh@Wh + Xl@Wh + Xh@Wl + bias   (near-fp32)
// CTA tile 64x64, 128 threads (4 warps, each 32x32 via 2x4 m16n8k8 frags).
// K chunk 16, double-buffered cp.async. Inner loop = pure LDS + MMA.
// ---------------------------------------------------------------------------
#define GBM 64
#define GBN 64
#define GBK 16
#define APAD 20
#define BPAD 72

__device__ __forceinline__ void cp16(void* smem, const void* g) {
    uint32_t s = (uint32_t)__cvta_generic_to_shared(smem);
    asm volatile("cp.async.cg.shared.global [%0], [%1], 16;\n" :: "r"(s), "l"(g));
}
__device__ __forceinline__ void mma_tf32(float* acc, const uint32_t* a, const uint32_t* b) {
    asm volatile(
        "mma.sync.aligned.m16n8k8.row.col.f32.tf32.tf32.f32 "
        "{%0,%1,%2,%3}, {%4,%5,%6,%7}, {%8,%9}, {%0,%1,%2,%3};\n"
        : "+f"(acc[0]), "+f"(acc[1]), "+f"(acc[2]), "+f"(acc[3])
        : "r"(a[0]), "r"(a[1]), "r"(a[2]), "r"(a[3]), "r"(b[0]), "r"(b[1]));
}

__global__ __launch_bounds__(128) void gemm_tc_kernel(
    const float* __restrict__ Xh, const float* __restrict__ Xl,
    const float* __restrict__ Whb, const float* __restrict__ Wlb,
    const float* __restrict__ b0, float* __restrict__ Y0,
    const float* __restrict__ b1, float* __restrict__ Y1,
    const float* __restrict__ b2, float* __restrict__ Y2)
{
    __shared__ float Ah[2][GBM][APAD];
    __shared__ float Al[2][GBM][APAD];
    __shared__ float Bh[2][GBK][BPAD];
    __shared__ float Bl[2][GBK][BPAD];

    const int t    = threadIdx.x;
    const int lane = t & 31;
    const int warp = t >> 5;
    const int warp_m = warp & 1;
    const int warp_n = warp >> 1;

    const int bm = blockIdx.x * GBM;
    const int wsel = blockIdx.y >> 2;
    const int bn = (blockIdx.y & 3) * GBN;

    const float* Wh   = Whb + wsel * WSZ;
    const float* Wl   = Wlb + wsel * WSZ;
    const float* bias = (wsel == 0) ? b0 : ((wsel == 1) ? b1 : b2);
    float*       Y    = (wsel == 0) ? Y0 : ((wsel == 1) ? Y1 : Y2);

    float acc[2][4][4];
#pragma unroll
    for (int mf = 0; mf < 2; ++mf)
#pragma unroll
        for (int nf = 0; nf < 4; ++nf)
#pragma unroll
            for (int r = 0; r < 4; ++r) acc[mf][nf][r] = 0.f;

    // Loader: A 64x16 = 256 float4 (2/thr per half), B 16x64 = 256 float4
    const int am  = t >> 2;                 // A: rows t>>2 and +32
    const int akq = (t & 3) * 4;
    const int bkk = t >> 4;                 // B: k rows t>>4 and +8
    const int bnq = (t & 15) * 4;

#define LOAD_TILE(it, buf)                                                         \
    do {                                                                           \
        int k0_ = (it) * GBK;                                                      \
        cp16(&Ah[buf][am][akq],      &Xh[(bm + am) * Edim + k0_ + akq]);           \
        cp16(&Ah[buf][am + 32][akq], &Xh[(bm + am + 32) * Edim + k0_ + akq]);      \
        cp16(&Al[buf][am][akq],      &Xl[(bm + am) * Edim + k0_ + akq]);           \
        cp16(&Al[buf][am + 32][akq], &Xl[(bm + am + 32) * Edim + k0_ + akq]);      \
        cp16(&Bh[buf][bkk][bnq],     &Wh[(k0_ + bkk) * Edim + bn + bnq]);          \
        cp16(&Bh[buf][bkk + 8][bnq], &Wh[(k0_ + bkk + 8) * Edim + bn + bnq]);      \
        cp16(&Bl[buf][bkk][bnq],     &Wl[(k0_ + bkk) * Edim + bn + bnq]);          \
        cp16(&Bl[buf][bkk + 8][bnq], &Wl[(k0_ + bkk + 8) * Edim + bn + bnq]);      \
        asm volatile("cp.async.commit_group;\n");                                  \
    } while (0)

    LOAD_TILE(0, 0);

    const int KITERS = Edim / GBK;   // 16
    for (int it = 0; it < KITERS; ++it) {
        int buf = it & 1;
        if (it + 1 < KITERS) {
            LOAD_TILE(it + 1, buf ^ 1);
            asm volatile("cp.async.wait_group 1;\n");
        } else {
            asm volatile("cp.async.wait_group 0;\n");
        }
        __syncthreads();

#pragma unroll
        for (int ks = 0; ks < 2; ++ks) {
            const int kk = ks * 8 + (lane & 3);
            uint32_t ah[2][4], al[2][4], bh[4][2], bl[4][2];
#pragma unroll
            for (int mf = 0; mf < 2; ++mf) {
                int r = warp_m * 32 + mf * 16 + (lane >> 2);
                ah[mf][0] = __float_as_uint(Ah[buf][r][kk]);
                ah[mf][1] = __float_as_uint(Ah[buf][r + 8][kk]);
                ah[mf][2] = __float_as_uint(Ah[buf][r][kk + 4]);
                ah[mf][3] = __float_as_uint(Ah[buf][r + 8][kk + 4]);
                al[mf][0] = __float_as_uint(Al[buf][r][kk]);
                al[mf][1] = __float_as_uint(Al[buf][r + 8][kk]);
                al[mf][2] = __float_as_uint(Al[buf][r][kk + 4]);
                al[mf][3] = __float_as_uint(Al[buf][r + 8][kk + 4]);
            }
#pragma unroll
            for (int nf = 0; nf < 4; ++nf) {
                int cn = warp_n * 32 + nf * 8 + (lane >> 2);
                bh[nf][0] = __float_as_uint(Bh[buf][kk][cn]);
                bh[nf][1] = __float_as_uint(Bh[buf][kk + 4][cn]);
                bl[nf][0] = __float_as_uint(Bl[buf][kk][cn]);
                bl[nf][1] = __float_as_uint(Bl[buf][kk + 4][cn]);
            }
#pragma unroll
            for (int mf = 0; mf < 2; ++mf)
#pragma unroll
                for (int nf = 0; nf < 4; ++nf) {
                    mma_tf32(acc[mf][nf], al[mf], bh[nf]);   // lo*hi
                    mma_tf32(acc[mf][nf], ah[mf], bl[nf]);   // hi*lo
                    mma_tf32(acc[mf][nf], ah[mf], bh[nf]);   // hi*hi
                }
        }
        __syncthreads();
    }

    // ---- epilogue: bias + store ----
#pragma unroll
    for (int mf = 0; mf < 2; ++mf) {
        int r = bm + warp_m * 32 + mf * 16 + (lane >> 2);
#pragma unroll
        for (int nf = 0; nf < 4; ++nf) {
            int cg = bn + warp_n * 32 + nf * 8 + 2 * (lane & 3);
            float bv0 = bias[cg], bv1 = bias[cg + 1];
            float2 v0 = make_float2(acc[mf][nf][0] + bv0, acc[mf][nf][1] + bv1);
            float2 v1 = make_float2(acc[mf][nf][2] + bv0, acc[mf][nf][3] + bv1);
            *(float2*)&Y[r * Edim + cg] = v0;
            *(float2*)&Y[(r + 8) * Edim + cg] = v1;
        }
    }
#undef LOAD_TILE
}

// ---------------------------------------------------------------------------
// Windowed attention. Block: 256 thr (8 warps), TS=32 positions per (b,h).
// Emits ctx as pre-split hi/lo for the O projection.
// ---------------------------------------------------------------------------
#define TS 32
#define ROWS (TS + 128)          // 160
#define RP 33                    // padded row stride

__global__ __launch_bounds__(256) void attn_kernel(
    const float* __restrict__ q, const float* __restrict__ k,
    const float* __restrict__ v,
    float* __restrict__ ctx_h, float* __restrict__ ctx_l,
    float* __restrict__ attn_out)
{
    __shared__ float ks[ROWS * RP];
    __shared__ float vs[ROWS * RP];
    __shared__ float p_sm[8][132];

    const int b    = blockIdx.z;
    const int h    = blockIdx.y;
    const int s0   = blockIdx.x * TS;
    const int t    = threadIdx.x;
    const int lane = t & 31;
    const int warp = t >> 5;

    const int base = (b * Sdim) * Edim + h * HD;

#pragma unroll
    for (int it = 0; it < ROWS / 8; ++it) {
        int r = warp + it * 8;
        int tok = s0 - OFF + r;
        tok = min(max(tok, 0), Sdim - 1);
        int g = base + tok * Edim + lane;
        ks[r * RP + lane] = k[g];
        vs[r * RP + lane] = v[g];
    }
    __syncthreads();

    const float scale = 0.17677669529663689f;  // 1/sqrt(32)

    for (int i = 0; i < TS / 8; ++i) {
        int sl = warp * (TS / 8) + i;
        int s  = s0 + sl;
        float qd = q[base + s * Edim + lane];

        int r0 = (sl + lane +  0) * RP;
        int r1 = (sl + lane + 32) * RP;
        int r2 = (sl + lane + 64) * RP;
        int r3 = (sl + lane + 96) * RP;
        int r4 = min(sl + lane + 128, ROWS - 1) * RP;

        float sum0 = 0.f, sum1 = 0.f, sum2 = 0.f, sum3 = 0.f, sum4 = 0.f;
#pragma unroll
        for (int d = 0; d < HD; ++d) {
            float a = __shfl_sync(FULL, qd, d);
            sum0 = fmaf(a, ks[r0 + d], sum0);
            sum1 = fmaf(a, ks[r1 + d], sum1);
            sum2 = fmaf(a, ks[r2 + d], sum2);
            sum3 = fmaf(a, ks[r3 + d], sum3);
            sum4 = fmaf(a, ks[r4 + d], sum4);
        }

        float sc[5];
        {
            int w, idx;
            w = lane +  0; idx = s + w - OFF;
            sc[0] = (idx >= 0 && idx < Sdim) ? sum0 * scale : -1e9f;
            w = lane + 32; idx = s + w - OFF;
            sc[1] = (idx >= 0 && idx < Sdim) ? sum1 * scale : -1e9f;
            w = lane + 64; idx = s + w - OFF;
            sc[2] = (idx >= 0 && idx < Sdim) ? sum2 * scale : -1e9f;
            w = lane + 96; idx = s + w - OFF;
            sc[3] = (idx >= 0 && idx < Sdim) ? sum3 * scale : -1e9f;
            idx = s + 128 - OFF;
            sc[4] = (lane == 0) ? ((idx < Sdim) ? sum4 * scale : -1e9f)
                                : -INFINITY;
        }

        float m = sc[0];
#pragma unroll
        for (int j = 1; j < 5; ++j) m = fmaxf(m, sc[j]);
#pragma unroll
        for (int o = 16; o; o >>= 1) m = fmaxf(m, __shfl_xor_sync(FULL, m, o));

        float ex[5], lsum = 0.f;
#pragma unroll
        for (int j = 0; j < 5; ++j) { ex[j] = expf(sc[j] - m); lsum += ex[j]; }
#pragma unroll
        for (int o = 16; o; o >>= 1) lsum += __shfl_xor_sync(FULL, lsum, o);
        float inv = 1.f / lsum;

        int arow = ((b * Hn + h) * Sdim + s) * WIN;
#pragma unroll
        for (int j = 0; j < 4; ++j) {
            int w = lane + 32 * j;
            float p = ex[j] * inv;
            p_sm[warp][w] = p;
            if (attn_out) attn_out[arow + w] = p;
        }
        if (lane == 0) {
            float p = ex[4] * inv;
            p_sm[warp][128] = p;
            if (attn_out) attn_out[arow + 128] = p;
        }
        __syncwarp();

        float cacc = 0.f;
        int vb = sl * RP + lane;
#pragma unroll 8
        for (int w = 0; w < WIN; ++w)
            cacc = fmaf(p_sm[warp][w], vs[vb + w * RP], cacc);

        uint32_t chi, clo;
        split_tf32(cacc, chi, clo);
        ctx_h[base + s * Edim + lane] = __uint_as_float(chi);
        ctx_l[base + s * Edim + lane] = __uint_as_float(clo);
        __syncwarp();
    }
}

// ---------------------------------------------------------------------------
extern "C" void kernel_launch(void* const* d_in, const int* in_sizes, int n_in,
                              void* d_out, int out_size) {
    const float* x  = (const float*)d_in[0];
    const float* Wq = (const float*)d_in[1];
    const float* bq = (const float*)d_in[2];
    const float* Wk = (const float*)d_in[3];
    const float* bk = (const float*)d_in[4];
    const float* Wv = (const float*)d_in[5];
    const float* bv = (const float*)d_in[6];
    const float* Wo = (const float*)d_in[7];
    const float* bo = (const float*)d_in[8];
    float* out = (float*)d_out;

    float *xh, *xl, *q, *k, *v, *ch, *cl, *wh, *wl;
    cudaGetSymbolAddress((void**)&xh, g_xh);
    cudaGetSymbolAddress((void**)&xl, g_xl);
    cudaGetSymbolAddress((void**)&q,  g_q);
    cudaGetSymbolAddress((void**)&k,  g_k);
    cudaGetSymbolAddress((void**)&v,  g_v);
    cudaGetSymbolAddress((void**)&ch, g_ch);
    cudaGetSymbolAddress((void**)&cl, g_cl);
    cudaGetSymbolAddress((void**)&wh, g_wh);
    cudaGetSymbolAddress((void**)&wl, g_wl);

    const long OUT_ELEMS  = (long)Bz * Sdim * Edim;                 // 1,048,576
    const long ATTN_ELEMS = (long)Bz * Hn * Sdim * WIN;             // 4,227,072
    float* attn_out = nullptr;
    if ((long)out_size >= OUT_ELEMS + ATTN_ELEMS) attn_out = out + OUT_ELEMS;

    add_pe_kernel<<<MTOK * Edim / 256, 256>>>(x, xh, xl);
    split_w_kernel<<<4 * WSZ / 256, 256>>>(Wq, Wk, Wv, Wo, wh, wl);

    // Fused Q/K/V projections: grid.y 0-3 -> Wq, 4-7 -> Wk, 8-11 -> Wv
    gemm_tc_kernel<<<dim3(MTOK / GBM, 12), 128>>>(
        xh, xl, wh, wl, bq, q, bk, k, bv, v);

    attn_kernel<<<dim3(Sdim / TS, Hn, Bz), 256>>>(q, k, v, ch, cl, attn_out);

    // Output projection: grid.y 0-3 -> Wo (index 3 in packed weights)
    gemm_tc_kernel<<<dim3(MTOK / GBM, 4), 128>>>(
        ch, cl, wh + 3 * WSZ, wl + 3 * WSZ, bo, out, bo, out, bo, out);
}

// round 8
// speedup vs baseline: 1.3496x; 1.3496x over previous
#include <cuda_runtime.h>
#include <math.h>
#include <stdint.h>

#define FULL 0xffffffffu

// Problem constants
#define Bz 2
#define Sdim 2048
#define Edim 256
#define Hn 8
#define HD 32
#define WIN 129
#define OFF 64
#define MTOK (Bz*Sdim)          // 4096 token rows

// Scratch (no cudaMalloc allowed)
__device__ float g_xpe[MTOK*Edim];
__device__ float g_q[MTOK*Edim];
__device__ float g_k[MTOK*Edim];
__device__ float g_v[MTOK*Edim];
__device__ float g_ctx[MTOK*Edim];

__device__ __forceinline__ void split_tf32(float x, uint32_t& hi, uint32_t& lo) {
    asm("cvt.rna.tf32.f32 %0, %1;" : "=r"(hi) : "f"(x));
    float l = x - __uint_as_float(hi);
    asm("cvt.rna.tf32.f32 %0, %1;" : "=r"(lo) : "f"(l));
}
__device__ __forceinline__ void mma_tf32(float* acc, const uint32_t* a, const uint32_t* b) {
    asm volatile(
        "mma.sync.aligned.m16n8k8.row.col.f32.tf32.tf32.f32 "
        "{%0,%1,%2,%3}, {%4,%5,%6,%7}, {%8,%9}, {%0,%1,%2,%3};\n"
        : "+f"(acc[0]), "+f"(acc[1]), "+f"(acc[2]), "+f"(acc[3])
        : "r"(a[0]), "r"(a[1]), "r"(a[2]), "r"(a[3]), "r"(b[0]), "r"(b[1]));
}

// ---------------------------------------------------------------------------
// x + sinusoidal positional encoding
// ---------------------------------------------------------------------------
__global__ void add_pe_kernel(const float* __restrict__ x, float* __restrict__ y) {
    int i = blockIdx.x * 256 + threadIdx.x;
    int e = i & (Edim - 1);
    int s = (i >> 8) & (Sdim - 1);
    float dv = expf((float)(e >> 1) * (-2.0f * 9.210340371976184f / 256.0f));
    float ang = (float)s * dv;
    float pe = (e & 1) ? cosf(ang) : sinf(ang);
    y[i] = x[i] + pe;
}

// ---------------------------------------------------------------------------
// 3xTF32 tensor-core GEMM (R6 config): Y[M,256] = X[M,256] @ W[256,256] + bias
// CTA tile 64x64, 128 threads (4 warps, each 32x32 via 2x4 m16n8k8 frags).
// K chunk 32, double-buffered cp.async. QKV fused via grid.y.
// ---------------------------------------------------------------------------
#define GBM 64
#define GBN 64
#define GBK 32
#define APAD 36
#define BPAD 72

__device__ __forceinline__ void cp16(void* smem, const void* g) {
    uint32_t s = (uint32_t)__cvta_generic_to_shared(smem);
    asm volatile("cp.async.cg.shared.global [%0], [%1], 16;\n" :: "r"(s), "l"(g));
}

__global__ __launch_bounds__(128) void gemm_tc_kernel(
    const float* __restrict__ X,
    const float* __restrict__ W0, const float* __restrict__ b0, float* __restrict__ Y0,
    const float* __restrict__ W1, const float* __restrict__ b1, float* __restrict__ Y1,
    const float* __restrict__ W2, const float* __restrict__ b2, float* __restrict__ Y2)
{
    __shared__ float As[2][GBM][APAD];
    __shared__ float Bs[2][GBK][BPAD];

    const int t    = threadIdx.x;
    const int lane = t & 31;
    const int warp = t >> 5;
    const int warp_m = warp & 1;
    const int warp_n = warp >> 1;

    const int bm = blockIdx.x * GBM;
    const int wsel = blockIdx.y >> 2;
    const int bn = (blockIdx.y & 3) * GBN;

    const float* W    = (wsel == 0) ? W0 : ((wsel == 1) ? W1 : W2);
    const float* bias = (wsel == 0) ? b0 : ((wsel == 1) ? b1 : b2);
    float*       Y    = (wsel == 0) ? Y0 : ((wsel == 1) ? Y1 : Y2);

    float acc[2][4][4];
#pragma unroll
    for (int mf = 0; mf < 2; ++mf)
#pragma unroll
        for (int nf = 0; nf < 4; ++nf)
#pragma unroll
            for (int r = 0; r < 4; ++r) acc[mf][nf][r] = 0.f;

#define LOAD_TILE(it, buf)                                                       \
    do {                                                                         \
        int k0_ = (it) * GBK;                                                    \
        _Pragma("unroll")                                                        \
        for (int c = 0; c < 4; ++c) {                                            \
            int f = t + c * 128;                                                 \
            int m_ = f >> 3, kq_ = (f & 7) << 2;                                 \
            cp16(&As[buf][m_][kq_], &X[(bm + m_) * Edim + k0_ + kq_]);           \
        }                                                                        \
        _Pragma("unroll")                                                        \
        for (int c = 0; c < 4; ++c) {                                            \
            int f = t + c * 128;                                                 \
            int kk_ = f >> 4, nq_ = (f & 15) << 2;                               \
            cp16(&Bs[buf][kk_][nq_], &W[(k0_ + kk_) * Edim + bn + nq_]);         \
        }                                                                        \
        asm volatile("cp.async.commit_group;\n");                                \
    } while (0)

    LOAD_TILE(0, 0);

    const int KITERS = Edim / GBK;   // 8
    for (int it = 0; it < KITERS; ++it) {
        int buf = it & 1;
        if (it + 1 < KITERS) {
            LOAD_TILE(it + 1, buf ^ 1);
            asm volatile("cp.async.wait_group 1;\n");
        } else {
            asm volatile("cp.async.wait_group 0;\n");
        }
        __syncthreads();

#pragma unroll
        for (int ks = 0; ks < 4; ++ks) {
            const int kk = ks * 8 + (lane & 3);
            uint32_t ah[2][4], al[2][4], bh[4][2], bl[4][2];
#pragma unroll
            for (int mf = 0; mf < 2; ++mf) {
                int r = warp_m * 32 + mf * 16 + (lane >> 2);
                split_tf32(As[buf][r][kk],          ah[mf][0], al[mf][0]);
                split_tf32(As[buf][r + 8][kk],      ah[mf][1], al[mf][1]);
                split_tf32(As[buf][r][kk + 4],      ah[mf][2], al[mf][2]);
                split_tf32(As[buf][r + 8][kk + 4],  ah[mf][3], al[mf][3]);
            }
#pragma unroll
            for (int nf = 0; nf < 4; ++nf) {
                int cn = warp_n * 32 + nf * 8 + (lane >> 2);
                split_tf32(Bs[buf][kk][cn],     bh[nf][0], bl[nf][0]);
                split_tf32(Bs[buf][kk + 4][cn], bh[nf][1], bl[nf][1]);
            }
#pragma unroll
            for (int mf = 0; mf < 2; ++mf)
#pragma unroll
                for (int nf = 0; nf < 4; ++nf) {
                    mma_tf32(acc[mf][nf], al[mf], bh[nf]);
                    mma_tf32(acc[mf][nf], ah[mf], bl[nf]);
                    mma_tf32(acc[mf][nf], ah[mf], bh[nf]);
                }
        }
        __syncthreads();
    }

#pragma unroll
    for (int mf = 0; mf < 2; ++mf) {
        int r = bm + warp_m * 32 + mf * 16 + (lane >> 2);
#pragma unroll
        for (int nf = 0; nf < 4; ++nf) {
            int cg = bn + warp_n * 32 + nf * 8 + 2 * (lane & 3);
            float bv0 = bias[cg], bv1 = bias[cg + 1];
            float2 v0 = make_float2(acc[mf][nf][0] + bv0, acc[mf][nf][1] + bv1);
            float2 v1 = make_float2(acc[mf][nf][2] + bv0, acc[mf][nf][3] + bv1);
            *(float2*)&Y[r * Edim + cg] = v0;
            *(float2*)&Y[(r + 8) * Edim + cg] = v1;
        }
    }
#undef LOAD_TILE
}

// ---------------------------------------------------------------------------
// Tensor-core windowed attention.
// Block: 256 thr (8 warps), 32 queries for one (b,h). Key rows 160.
// S(32x160) = Q @ K^T (3xTF32), band mask, register softmax, P -> smem,
// ctx(32x32) = P @ V (3xTF32).
// Warp grid 2x4: warp_m = warp&1 (16 queries), warp_n = warp>>2.. (keys/dims).
// ---------------------------------------------------------------------------
#define KP 36     // k_sm / q_sm row pad
#define VP 40     // v_sm row pad
#define PP 164    // p_sm row pad
#define NROWS 160

// float offsets into dynamic smem
#define SM_K 0
#define SM_V (SM_K + NROWS*KP)            // 5760
#define SM_Q (SM_V + NROWS*VP)            // 12160
#define SM_P (SM_Q + 32*KP)               // 13312
#define SM_RMAX (SM_P + 32*PP)            // 18560
#define SM_RSUM (SM_RMAX + 128)           // 18688
#define SM_TOT (SM_RSUM + 128)            // 18816 floats = 75264 B

__global__ __launch_bounds__(256) void attn_kernel(
    const float* __restrict__ q, const float* __restrict__ k,
    const float* __restrict__ v, float* __restrict__ ctx,
    float* __restrict__ attn_out)
{
    extern __shared__ float sm[];
    float* k_sm = sm + SM_K;
    float* v_sm = sm + SM_V;
    float* q_sm = sm + SM_Q;
    float* p_sm = sm + SM_P;
    float* rmax = sm + SM_RMAX;
    float* rsum = sm + SM_RSUM;

    const int b    = blockIdx.z;
    const int h    = blockIdx.y;
    const int s0   = blockIdx.x * 32;
    const int t    = threadIdx.x;
    const int lane = t & 31;
    const int warp = t >> 5;
    const int warp_m = warp & 1;     // 16-query group
    const int warp_n = warp >> 1;    // 4 groups: 40 keys each (scores) / 8 dims (ctx)
    const int lr = lane >> 2;        // 0..7
    const int lc = lane & 3;         // 0..3

    const int base = (b * Sdim) * Edim + h * HD;

    // ---- stage K, V (160 rows) and Q (32 rows), fp32, conflict-free pads ----
#pragma unroll
    for (int it = 0; it < NROWS / 8; ++it) {
        int r = warp + it * 8;
        int tok = min(max(s0 - OFF + r, 0), Sdim - 1);
        int g = base + tok * Edim + lane;
        k_sm[r * KP + lane] = k[g];
        v_sm[r * VP + lane] = v[g];
    }
    {
        int qq = warp * 4;
#pragma unroll
        for (int i = 0; i < 4; ++i)
            q_sm[(qq + i) * KP + lane] = q[base + (s0 + qq + i) * Edim + lane];
    }
    __syncthreads();

    // ---- scores: per warp S[16 q][40 keys] = 5 n-tiles x 4 k-tiles ----
    float acc[5][4];
#pragma unroll
    for (int nt = 0; nt < 5; ++nt)
#pragma unroll
        for (int j = 0; j < 4; ++j) acc[nt][j] = 0.f;

#pragma unroll
    for (int kt = 0; kt < 4; ++kt) {
        int kb = kt * 8 + lc;
        uint32_t ah[4], al[4];
        split_tf32(q_sm[(warp_m*16 + lr    ) * KP + kb    ], ah[0], al[0]);
        split_tf32(q_sm[(warp_m*16 + lr + 8) * KP + kb    ], ah[1], al[1]);
        split_tf32(q_sm[(warp_m*16 + lr    ) * KP + kb + 4], ah[2], al[2]);
        split_tf32(q_sm[(warp_m*16 + lr + 8) * KP + kb + 4], ah[3], al[3]);
#pragma unroll
        for (int nt = 0; nt < 5; ++nt) {
            int key = warp_n * 40 + nt * 8 + lr;
            uint32_t bh[2], bl[2];
            split_tf32(k_sm[key * KP + kb    ], bh[0], bl[0]);
            split_tf32(k_sm[key * KP + kb + 4], bh[1], bl[1]);
            mma_tf32(acc[nt], al, bh);
            mma_tf32(acc[nt], ah, bl);
            mma_tf32(acc[nt], ah, bh);
        }
    }

    // ---- scale + band/sequence mask; row maxima ----
    const float scale = 0.17677669529663689f;  // 1/sqrt(32)
    const int q0 = warp_m * 16 + lr;           // rows for j=0,1
    const int q1 = q0 + 8;                     // rows for j=2,3
    float m0 = -INFINITY, m1 = -INFINITY;
#pragma unroll
    for (int nt = 0; nt < 5; ++nt) {
#pragma unroll
        for (int j = 0; j < 4; ++j) {
            int row = (j >= 2) ? q1 : q0;
            int key = warp_n * 40 + nt * 8 + 2 * lc + (j & 1);
            int w  = key - row;
            int kg = s0 - OFF + key;
            bool valid = (w >= 0) & (w <= 128) & (kg >= 0) & (kg < Sdim);
            float s = valid ? acc[nt][j] * scale : -1e9f;
            acc[nt][j] = s;
            if (j >= 2) m1 = fmaxf(m1, s); else m0 = fmaxf(m0, s);
        }
    }
    m0 = fmaxf(m0, __shfl_xor_sync(FULL, m0, 1));
    m0 = fmaxf(m0, __shfl_xor_sync(FULL, m0, 2));
    m1 = fmaxf(m1, __shfl_xor_sync(FULL, m1, 1));
    m1 = fmaxf(m1, __shfl_xor_sync(FULL, m1, 2));
    if (lc == 0) { rmax[q0 * 4 + warp_n] = m0; rmax[q1 * 4 + warp_n] = m1; }
    __syncthreads();

    float4 t0 = *(const float4*)&rmax[q0 * 4];
    float4 t1 = *(const float4*)&rmax[q1 * 4];
    float gm0 = fmaxf(fmaxf(t0.x, t0.y), fmaxf(t0.z, t0.w));
    float gm1 = fmaxf(fmaxf(t1.x, t1.y), fmaxf(t1.z, t1.w));

    float sum0 = 0.f, sum1 = 0.f;
#pragma unroll
    for (int nt = 0; nt < 5; ++nt) {
#pragma unroll
        for (int j = 0; j < 4; ++j) {
            float e = expf(acc[nt][j] - ((j >= 2) ? gm1 : gm0));
            acc[nt][j] = e;
            if (j >= 2) sum1 += e; else sum0 += e;
        }
    }
    sum0 += __shfl_xor_sync(FULL, sum0, 1);
    sum0 += __shfl_xor_sync(FULL, sum0, 2);
    sum1 += __shfl_xor_sync(FULL, sum1, 1);
    sum1 += __shfl_xor_sync(FULL, sum1, 2);
    if (lc == 0) { rsum[q0 * 4 + warp_n] = sum0; rsum[q1 * 4 + warp_n] = sum1; }
    __syncthreads();

    float4 u0 = *(const float4*)&rsum[q0 * 4];
    float4 u1 = *(const float4*)&rsum[q1 * 4];
    float inv0 = 1.f / (u0.x + u0.y + u0.z + u0.w);
    float inv1 = 1.f / (u1.x + u1.y + u1.z + u1.w);

    // ---- normalized P -> smem ----
#pragma unroll
    for (int nt = 0; nt < 5; ++nt) {
#pragma unroll
        for (int j = 0; j < 4; ++j) {
            int row = (j >= 2) ? q1 : q0;
            int key = warp_n * 40 + nt * 8 + 2 * lc + (j & 1);
            p_sm[row * PP + key] = acc[nt][j] * ((j >= 2) ? inv1 : inv0);
        }
    }
    __syncthreads();

    // ---- attention weights output (coalesced from smem) ----
    if (attn_out) {
        int qrow = warp * 4;
#pragma unroll
        for (int i = 0; i < 4; ++i) {
            int qq = qrow + i;
            int arow = ((b * Hn + h) * Sdim + s0 + qq) * WIN;
#pragma unroll
            for (int j = 0; j < 4; ++j)
                attn_out[arow + lane + 32 * j] = p_sm[qq * PP + qq + lane + 32 * j];
            if (lane == 0)
                attn_out[arow + 128] = p_sm[qq * PP + qq + 128];
        }
    }

    // ---- ctx = P(32x160) @ V(160x32): warp covers 16 q x 8 d, 20 k-tiles ----
    float c[4] = {0.f, 0.f, 0.f, 0.f};
#pragma unroll
    for (int kt = 0; kt < 20; ++kt) {
        int kb = kt * 8 + lc;
        uint32_t ah[4], al[4], bh[2], bl[2];
        split_tf32(p_sm[q0 * PP + kb    ], ah[0], al[0]);
        split_tf32(p_sm[q1 * PP + kb    ], ah[1], al[1]);
        split_tf32(p_sm[q0 * PP + kb + 4], ah[2], al[2]);
        split_tf32(p_sm[q1 * PP + kb + 4], ah[3], al[3]);
        split_tf32(v_sm[(kb    ) * VP + warp_n * 8 + lr], bh[0], bl[0]);
        split_tf32(v_sm[(kb + 4) * VP + warp_n * 8 + lr], bh[1], bl[1]);
        mma_tf32(c, al, bh);
        mma_tf32(c, ah, bl);
        mma_tf32(c, ah, bh);
    }

    int dcol = warp_n * 8 + 2 * lc;
    *(float2*)&ctx[base + (s0 + q0) * Edim + dcol] = make_float2(c[0], c[1]);
    *(float2*)&ctx[base + (s0 + q1) * Edim + dcol] = make_float2(c[2], c[3]);
}

// ---------------------------------------------------------------------------
extern "C" void kernel_launch(void* const* d_in, const int* in_sizes, int n_in,
                              void* d_out, int out_size) {
    const float* x  = (const float*)d_in[0];
    const float* Wq = (const float*)d_in[1];
    const float* bq = (const float*)d_in[2];
    const float* Wk = (const float*)d_in[3];
    const float* bk = (const float*)d_in[4];
    const float* Wv = (const float*)d_in[5];
    const float* bv = (const float*)d_in[6];
    const float* Wo = (const float*)d_in[7];
    const float* bo = (const float*)d_in[8];
    float* out = (float*)d_out;

    float *xpe, *q, *k, *v, *ctx;
    cudaGetSymbolAddress((void**)&xpe, g_xpe);
    cudaGetSymbolAddress((void**)&q,   g_q);
    cudaGetSymbolAddress((void**)&k,   g_k);
    cudaGetSymbolAddress((void**)&v,   g_v);
    cudaGetSymbolAddress((void**)&ctx, g_ctx);

    const long OUT_ELEMS  = (long)Bz * Sdim * Edim;                 // 1,048,576
    const long ATTN_ELEMS = (long)Bz * Hn * Sdim * WIN;             // 4,227,072
    float* attn_out = nullptr;
    if ((long)out_size >= OUT_ELEMS + ATTN_ELEMS) attn_out = out + OUT_ELEMS;

    static bool attr_set = false;
    if (!attr_set) {
        cudaFuncSetAttribute(attn_kernel,
                             cudaFuncAttributeMaxDynamicSharedMemorySize,
                             SM_TOT * 4);
        attr_set = true;
    }

    add_pe_kernel<<<MTOK * Edim / 256, 256>>>(x, xpe);

    // Fused Q/K/V projections: grid.y 0-3 -> Wq, 4-7 -> Wk, 8-11 -> Wv
    gemm_tc_kernel<<<dim3(MTOK / GBM, 12), 128>>>(
        xpe, Wq, bq, q, Wk, bk, k, Wv, bv, v);

    attn_kernel<<<dim3(Sdim / 32, Hn, Bz), 256, SM_TOT * 4>>>(
        q, k, v, ctx, attn_out);

    // Output projection: grid.y 0-3 -> Wo only
    gemm_tc_kernel<<<dim3(MTOK / GBM, 4), 128>>>(
        ctx, Wo, bo, out, Wo, bo, out, Wo, bo, out);
}